// round 15
// baseline (speedup 1.0000x reference)
#include <cuda_runtime.h>
#include <cuda_fp16.h>
#include <cstdint>

#define BB 4
#define SS 4096
#define EE 1024
#define DD 128
#define QSCALE (0.03125f * 1.4426950408889634f)   // (1/sqrt(1024)) * log2(e)

// ---------------- device scratch ----------------
__device__ __align__(16) __half g_Wh[3*EE*DD];     // [o][e][n] fp16
__device__ __align__(16) __half g_Qh[BB*SS*DD];    // pre-scaled by QSCALE
__device__ __align__(16) __half g_Kh[BB*SS*DD];
__device__ __align__(16) __half g_Vh[BB*SS*DD];
__device__ __align__(16) float  g_Opart[(size_t)BB*32*4*128*128];  // [b][qt][slot][128][128]
__device__ __align__(16) float  g_lpart[BB*32*4*128];              // [b][qt][slot][row]

// ---------------- helpers ----------------
__device__ __forceinline__ uint32_t smem_u32(const void* p) {
    uint32_t a;
    asm("{ .reg .u64 t; cvta.to.shared.u64 t, %1; cvt.u32.u64 %0, t; }" : "=r"(a) : "l"(p));
    return a;
}
__device__ __forceinline__ void ldsm4(uint32_t& r0, uint32_t& r1, uint32_t& r2, uint32_t& r3, uint32_t addr) {
    asm volatile("ldmatrix.sync.aligned.m8n8.x4.shared.b16 {%0,%1,%2,%3}, [%4];"
        : "=r"(r0), "=r"(r1), "=r"(r2), "=r"(r3) : "r"(addr));
}
__device__ __forceinline__ void ldsm4t(uint32_t& r0, uint32_t& r1, uint32_t& r2, uint32_t& r3, uint32_t addr) {
    asm volatile("ldmatrix.sync.aligned.m8n8.x4.trans.shared.b16 {%0,%1,%2,%3}, [%4];"
        : "=r"(r0), "=r"(r1), "=r"(r2), "=r"(r3) : "r"(addr));
}
__device__ __forceinline__ void mma16816(float* d, const uint32_t* a, uint32_t b0, uint32_t b1) {
    asm volatile("mma.sync.aligned.m16n8k16.row.col.f32.f16.f16.f32 "
        "{%0,%1,%2,%3},{%4,%5,%6,%7},{%8,%9},{%0,%1,%2,%3};"
        : "+f"(d[0]), "+f"(d[1]), "+f"(d[2]), "+f"(d[3])
        : "r"(a[0]), "r"(a[1]), "r"(a[2]), "r"(a[3]), "r"(b0), "r"(b1));
}
// fp16-accumulator MMA: D,C are 2x uint32 (half2 pairs)
__device__ __forceinline__ void mma16816h(uint32_t* d, const uint32_t* a, uint32_t b0, uint32_t b1) {
    asm volatile("mma.sync.aligned.m16n8k16.row.col.f16.f16.f16.f16 "
        "{%0,%1},{%2,%3,%4,%5},{%6,%7},{%0,%1};"
        : "+r"(d[0]), "+r"(d[1])
        : "r"(a[0]), "r"(a[1]), "r"(a[2]), "r"(a[3]), "r"(b0), "r"(b1));
}
__device__ __forceinline__ void cpa16(uint32_t dst, const void* src) {
    asm volatile("cp.async.ca.shared.global [%0], [%1], 16;" :: "r"(dst), "l"(src));
}
#define CPC()  asm volatile("cp.async.commit_group;" ::: "memory")
#define CPW0() asm volatile("cp.async.wait_group 0;" ::: "memory")
#define CPW1() asm volatile("cp.async.wait_group 1;" ::: "memory")

__device__ __forceinline__ uint32_t packh2(float lo, float hi) {
    __half2 h = __floats2half2_rn(lo, hi);
    return *(uint32_t*)&h;
}
// 2^x on a packed half2 (one MUFU op)
__device__ __forceinline__ uint32_t ex2h2(uint32_t x) {
    uint32_t d;
    asm("ex2.approx.f16x2 %0, %1;" : "=r"(d) : "r"(x));
    return d;
}
__device__ __forceinline__ uint32_t hadd2(uint32_t a, uint32_t b) {
    uint32_t d;
    asm("add.rn.f16x2 %0, %1, %2;" : "=r"(d) : "r"(a), "r"(b));
    return d;
}

// ---------------- W convert (vectorized) ----------------
__global__ void wconv_kernel(const float* __restrict__ Wq, const float* __restrict__ Wk,
                             const float* __restrict__ Wv)
{
    int i4 = blockIdx.x * blockDim.x + threadIdx.x;
    if (i4 >= 3 * EE * DD / 4) return;
    int o = i4 >> 15, r = i4 & 32767;
    const float* W = (o == 0) ? Wq : (o == 1) ? Wk : Wv;
    float4 v = ((const float4*)W)[r];
    uint2 h;
    h.x = packh2(v.x, v.y);
    h.y = packh2(v.z, v.w);
    ((uint2*)(g_Wh + (size_t)o * EE * DD))[r] = h;
}

// ---------------- projection: Y[m,128] = X[m,1024] @ W ----------------
#define PXSTR 72
#define PWSTR 136
#define PX_TILE (128*PXSTR)         // halves, x2 buffers
#define PW_TILE (64*PWSTR)          // halves, x2 buffers
#define PJ_SMEM ((2*PX_TILE + 2*PW_TILE)*2)   // 71,680 bytes

__global__ __launch_bounds__(256, 2) void proj_mma(const float* __restrict__ X)
{
    extern __shared__ __align__(16) __half sm[];
    __half* Xh = sm;                       // 2 buffers
    __half* Wh = sm + 2 * PX_TILE;         // 2 buffers

    const int tid  = threadIdx.x;
    const int lane = tid & 31;
    const int warp = tid >> 5;
    const int o = blockIdx.x, mt = blockIdx.y;
    const int m0 = mt * 128;

    const int xrow = tid >> 1;
    const int xcol = (tid & 1) * 32;
    const float* xbase = X + (size_t)(m0 + xrow) * EE + xcol;
    const __half* wh_src = g_Wh + (size_t)o * EE * DD;   // [e][n]

    // ---- prologue: X0 -> xb0, issue W0 ----
    float4 xr[8];
#pragma unroll
    for (int j = 0; j < 8; j++) xr[j] = ((const float4*)xbase)[j];
    {
        __half* xh = Xh + xrow * PXSTR + xcol;
#pragma unroll
        for (int j = 0; j < 8; j++) {
            float4 v = xr[j];
            ((uint32_t*)(xh + j * 4))[0] = packh2(v.x, v.y);
            ((uint32_t*)(xh + j * 4))[1] = packh2(v.z, v.w);
        }
    }
#pragma unroll
    for (int j = 0; j < 4; j++) {
        int idx = tid + j * 256;
        int r = idx >> 4, c8 = (idx & 15) * 8;
        cpa16(smem_u32(Wh + r * PWSTR + c8), wh_src + (size_t)r * DD + c8);
    }
    CPC();
#pragma unroll
    for (int j = 0; j < 8; j++) xr[j] = ((const float4*)(xbase + 64))[j];

    float acc[16][4];
#pragma unroll
    for (int i = 0; i < 16; i++)
#pragma unroll
        for (int j = 0; j < 4; j++) acc[i][j] = 0.f;

    const uint32_t lbX = (((uint32_t)(lane & 15)) * PXSTR + ((uint32_t)(lane >> 4)) * 8) * 2;
    const uint32_t lbW = (((uint32_t)(lane & 15)) * PWSTR + ((uint32_t)(lane >> 4)) * 8) * 2;

    for (int c = 0; c < 16; c++) {
        CPW0();            // W(c) data arrived
        __syncthreads();   // all warps done with compute(c-1): buffers (c+1)&1 now safe

        if (c + 1 < 16) {
            // STS X(c+1) into other buffer
            __half* xh = Xh + ((c + 1) & 1) * PX_TILE + xrow * PXSTR + xcol;
#pragma unroll
            for (int j = 0; j < 8; j++) {
                float4 v = xr[j];
                ((uint32_t*)(xh + j * 4))[0] = packh2(v.x, v.y);
                ((uint32_t*)(xh + j * 4))[1] = packh2(v.z, v.w);
            }
            // issue W(c+1) copy — overlaps with compute(c)
            const int nb = (c + 1) & 1;
#pragma unroll
            for (int j = 0; j < 4; j++) {
                int idx = tid + j * 256;
                int r = idx >> 4, c8 = (idx & 15) * 8;
                cpa16(smem_u32(Wh + nb * PW_TILE + r * PWSTR + c8),
                      wh_src + (size_t)((c + 1) * 64 + r) * DD + c8);
            }
            CPC();
            if (c + 2 < 16) {
#pragma unroll
                for (int j = 0; j < 8; j++) xr[j] = ((const float4*)(xbase + (c + 2) * 64))[j];
            }
        }

        const uint32_t xhb = smem_u32(Xh + (c & 1) * PX_TILE) + (uint32_t)warp * 16 * PXSTR * 2 + lbX;
        const uint32_t whb = smem_u32(Wh + (c & 1) * PW_TILE) + lbW;

        uint32_t afh[4][4];
#pragma unroll
        for (int j = 0; j < 4; j++)
            ldsm4(afh[j][0], afh[j][1], afh[j][2], afh[j][3], xhb + j * 32);
#pragma unroll
        for (int t2 = 0; t2 < 8; t2++) {
#pragma unroll
            for (int kk = 0; kk < 4; kk++) {
                uint32_t w0, w1, w2, w3;
                ldsm4t(w0, w1, w2, w3, whb + (uint32_t)kk * 16 * PWSTR * 2 + t2 * 32);
                mma16816(acc[2 * t2],     afh[kk], w0, w1);
                mma16816(acc[2 * t2 + 1], afh[kk], w2, w3);
            }
        }
    }

    // ---- epilogue ----
    const int r0 = m0 + warp * 16 + (lane >> 2);
    const int r1 = r0 + 8;
    __half* dst = (o == 0) ? g_Qh : (o == 1) ? g_Kh : g_Vh;
    const float sc = (o == 0) ? QSCALE : 1.0f;
#pragma unroll
    for (int nt = 0; nt < 16; nt++) {
        int cc = nt * 8 + (lane & 3) * 2;
        *(uint32_t*)(dst + (size_t)r0 * DD + cc) = packh2(acc[nt][0] * sc, acc[nt][1] * sc);
        *(uint32_t*)(dst + (size_t)r1 * DD + cc) = packh2(acc[nt][2] * sc, acc[nt][3] * sc);
    }
}

// ---------------- flash attention: 4 warps x 32 q-rows, ring-of-3 KV pairs ----------------
#define FSTR 136
#define FKV_TILE (64*FSTR)          // halves per 64-row tile (one ring slot)
#define FL_SMEM (6*FKV_TILE*2)      // 104,448 bytes (slots 0-1 initially hold Q)
#define HNEG 0xFBFFu                // fp16 -65504

__device__ __forceinline__ void cp_tile64(__half* dst, const __half* src, int tid) {
#pragma unroll
    for (int j = 0; j < 8; j++) {
        int idx = tid + j * 128;
        int r = idx >> 4, cc = (idx & 15) * 8;
        cpa16(smem_u32(dst + r * FSTR + cc), src + (size_t)r * DD + cc);
    }
}

// S-MMA (fp16 accumulate) for one 16-col sub-tile t: dst[rt][nh][rowhalf] as half2
__device__ __forceinline__ void s_mma_step(uint32_t (&dst)[2][2][2], uint32_t kbb, int t,
                                           const uint32_t (&qf)[2][8][4]) {
#pragma unroll
    for (int rt = 0; rt < 2; rt++)
#pragma unroll
        for (int nh = 0; nh < 2; nh++)
#pragma unroll
            for (int h = 0; h < 2; h++) dst[rt][nh][h] = 0u;
#pragma unroll
    for (int j = 0; j < 8; j++) {
        uint32_t k0, k1, k2, k3;
        ldsm4(k0, k1, k2, k3, kbb + (uint32_t)t * 16 * FSTR * 2 + j * 32);
        mma16816h(dst[0][0], qf[0][j], k0, k2);
        mma16816h(dst[0][1], qf[0][j], k1, k3);
        mma16816h(dst[1][0], qf[1][j], k0, k2);
        mma16816h(dst[1][1], qf[1][j], k1, k3);
    }
}

// PV-MMA for one 16-col sub-tile t: O += P_t @ V_t (fp32 accumulate)
__device__ __forceinline__ void pv_mma_step(float (&oa)[2][16][4], uint32_t vbb, int t,
                                            const uint32_t (&pf)[2][4]) {
#pragma unroll
    for (int t2 = 0; t2 < 8; t2++) {
        uint32_t v0, v1, v2, v3;
        ldsm4t(v0, v1, v2, v3, vbb + (uint32_t)t * 16 * FSTR * 2 + t2 * 32);
        mma16816(oa[0][2 * t2],     pf[0], v0, v1);
        mma16816(oa[0][2 * t2 + 1], pf[0], v2, v3);
        mma16816(oa[1][2 * t2],     pf[1], v0, v1);
        mma16816(oa[1][2 * t2 + 1], pf[1], v2, v3);
    }
}

// chunk units: s(qt) = ceil((qt+1)/9); grid = 296 = 2 CTAs x 148 SMs
__global__ __launch_bounds__(128, 2) void flash_mma(float* __restrict__ out)
{
    extern __shared__ __align__(16) __half sm[];
    const uint32_t smb = smem_u32(sm);

    const int tid  = threadIdx.x;
    const int lane = tid & 31;
    const int warp = tid >> 5;

    // pair heavy chunk i with light chunk 295-i on the same SM
    const int idx = (blockIdx.x < 148) ? blockIdx.x : (443 - blockIdx.x);
    const int bz = idx & 3;
    int v = idx >> 2;
    int qt = 31, s;
    for (;;) { s = (qt + 9) / 9; if (v < s) break; v -= s; qt--; }
    const int cidx = v;
    const int nn = qt + 1;
    const int cb_sz = nn / s, cb_rem = nn % s;
    const int t0 = cidx * cb_sz + (cidx < cb_rem ? cidx : cb_rem);
    const int sz128 = cb_sz + (cidx < cb_rem ? 1 : 0);
    const int u0 = 2 * t0;
    const int nit = 2 * sz128;          // iterations (>= 2)
    const int q0 = qt * 128;

    const __half* Qg = g_Qh + (size_t)(bz * SS + q0) * DD;
    const __half* Kg = g_Kh + (size_t)bz * SS * DD;
    const __half* Vg = g_Vh + (size_t)bz * SS * DD;

    // initial loads: Q -> slots 0,1 ; pair0 (K,V) -> slots 2,3 ; pair1 -> slots 4,5
    cp_tile64((__half*)sm,                Qg, tid);
    cp_tile64((__half*)sm + FKV_TILE,     Qg + (size_t)64 * DD, tid);
    cp_tile64((__half*)sm + 2 * FKV_TILE, Kg + (size_t)u0 * 64 * DD, tid);
    cp_tile64((__half*)sm + 3 * FKV_TILE, Vg + (size_t)u0 * 64 * DD, tid);
    CPC();   // group A: Q + pair0
    cp_tile64((__half*)sm + 4 * FKV_TILE, Kg + (size_t)(u0 + 1) * 64 * DD, tid);
    cp_tile64((__half*)sm + 5 * FKV_TILE, Vg + (size_t)(u0 + 1) * 64 * DD, tid);
    CPC();   // group B: pair1

    float o_acc[2][16][4];
#pragma unroll
    for (int rt = 0; rt < 2; rt++)
#pragma unroll
        for (int i = 0; i < 16; i++)
#pragma unroll
            for (int j = 0; j < 4; j++) o_acc[rt][i][j] = 0.f;
    float ls[2][2] = {{0.f, 0.f}, {0.f, 0.f}};

    const uint32_t lanebase = (((uint32_t)(lane & 15)) * FSTR + ((uint32_t)(lane >> 4)) * 8) * 2;
    const int rloc0 = warp * 32 + (lane >> 2);
    const int cl0 = (lane & 3) * 2;

    // ---- Q fragments (Q smem becomes ring slot 0/1 afterwards) ----
    uint32_t qf[2][8][4];
    CPW1();            // group A (Q + pair0) arrived
    __syncthreads();   // visible to all threads
#pragma unroll
    for (int rt = 0; rt < 2; rt++) {
        const uint32_t qb = smb + (uint32_t)(warp * 32 + rt * 16) * FSTR * 2 + lanebase;
#pragma unroll
        for (int j = 0; j < 8; j++)
            ldsm4(qf[rt][j][0], qf[rt][j][1], qf[rt][j][2], qf[rt][j][3], qb + j * 32);
    }

    for (int j = 0; j < nit; j++) {
        const int u = u0 + j;
        if (j < nit - 1) { CPW1(); } else { CPW0(); }
        __syncthreads();   // pair j visible; all warps done with pair j-1 (and qf loads on j=0)

        // prefetch pair j+2 into ring slot (j%3) — overlaps with compute below
        if (j + 2 < nit) {
            const int p = j % 3;
            cp_tile64((__half*)sm + (2 * p)     * FKV_TILE, Kg + (size_t)(u + 2) * 64 * DD, tid);
            cp_tile64((__half*)sm + (2 * p + 1) * FKV_TILE, Vg + (size_t)(u + 2) * 64 * DD, tid);
            CPC();
        }

        const int p = (j + 1) % 3;   // this iteration's pair: slots (2p, 2p+1)
        const uint32_t kbb = smb + (uint32_t)(2 * p) * FKV_TILE * 2 + lanebase;
        const uint32_t vbb = smb + (uint32_t)(2 * p + 1) * FKV_TILE * 2 + lanebase;
        const int kv0 = u * 64;
        const int dloc = u - 2 * qt;
        const bool diag = (dloc >= 0);
        const bool skipw = (dloc == 1) && (warp < 2);

        if (!skipw) {
            // per-tile half2 l accumulators (flushed to fp32 at tile end)
            uint32_t lh[2][2] = {{0u, 0u}, {0u, 0u}};
            // two-deep pipeline: per sub-tile issue S(t+1), PV(t-1), then softmax(t)
            uint32_t sf[2][2][2][2];   // S accumulators, ping-pong
            uint32_t pfb[2][2][4];     // P fragments, ping-pong
            s_mma_step(sf[0], kbb, 0, qf);
#pragma unroll
            for (int t = 0; t < 4; t++) {
                if (t < 3) s_mma_step(sf[(t + 1) & 1], kbb, t + 1, qf);
                if (t > 0) pv_mma_step(o_acc, vbb, t - 1, pfb[(t - 1) & 1]);

                // softmax(t): sf[t&1] -> pfb[t&1]
                uint32_t (&sc)[2][2][2] = sf[t & 1];
                uint32_t (&pf)[2][4] = pfb[t & 1];
#pragma unroll
                for (int rt = 0; rt < 2; rt++) {
                    if (diag) {
                        const int rg = q0 + rloc0 + rt * 16;
#pragma unroll
                        for (int nh = 0; nh < 2; nh++) {
                            const int cb = kv0 + t * 16 + nh * 8 + cl0;
                            uint32_t m0 = sc[rt][nh][0];
                            if (cb     > rg) m0 = (m0 & 0xFFFF0000u) | HNEG;
                            if (cb + 1 > rg) m0 = (m0 & 0x0000FFFFu) | (HNEG << 16);
                            sc[rt][nh][0] = m0;
                            uint32_t m1 = sc[rt][nh][1];
                            if (cb     > rg + 8) m1 = (m1 & 0xFFFF0000u) | HNEG;
                            if (cb + 1 > rg + 8) m1 = (m1 & 0x0000FFFFu) | (HNEG << 16);
                            sc[rt][nh][1] = m1;
                        }
                    }
                    pf[rt][0] = ex2h2(sc[rt][0][0]);   // row r,   k nh0
                    pf[rt][1] = ex2h2(sc[rt][0][1]);   // row r+8, k nh0
                    pf[rt][2] = ex2h2(sc[rt][1][0]);   // row r,   k nh1
                    pf[rt][3] = ex2h2(sc[rt][1][1]);   // row r+8, k nh1
                    lh[rt][0] = hadd2(lh[rt][0], hadd2(pf[rt][0], pf[rt][2]));
                    lh[rt][1] = hadd2(lh[rt][1], hadd2(pf[rt][1], pf[rt][3]));
                }
            }
            // drain: PV for t=3
            pv_mma_step(o_acc, vbb, 3, pfb[1]);

            // flush per-tile half2 sums into fp32 ls
#pragma unroll
            for (int rt = 0; rt < 2; rt++) {
#pragma unroll
                for (int k = 0; k < 2; k++) {
                    __half2 h = *(__half2*)&lh[rt][k];
                    float2 f = __half22float2(h);
                    ls[rt][k] += f.x + f.y;
                }
            }
        }
    }

    // ---- epilogue ----
#pragma unroll
    for (int rt = 0; rt < 2; rt++) {
        ls[rt][0] += __shfl_xor_sync(0xffffffffu, ls[rt][0], 1);
        ls[rt][0] += __shfl_xor_sync(0xffffffffu, ls[rt][0], 2);
        ls[rt][1] += __shfl_xor_sync(0xffffffffu, ls[rt][1], 1);
        ls[rt][1] += __shfl_xor_sync(0xffffffffu, ls[rt][1], 2);
    }

    if (s == 1) {
#pragma unroll
        for (int rt = 0; rt < 2; rt++) {
            const float inv0 = 1.0f / ls[rt][0];
            const float inv1 = 1.0f / ls[rt][1];
            float* o0 = out + (size_t)(bz * SS + q0 + rloc0 + rt * 16) * DD;
            float* o1 = o0 + 8 * DD;
#pragma unroll
            for (int nt = 0; nt < 16; nt++) {
                int cc = nt * 8 + cl0;
                *(float2*)(o0 + cc) = make_float2(o_acc[rt][nt][0] * inv0, o_acc[rt][nt][1] * inv0);
                *(float2*)(o1 + cc) = make_float2(o_acc[rt][nt][2] * inv1, o_acc[rt][nt][3] * inv1);
            }
        }
    } else {
        const int slot = (bz * 32 + qt) * 4 + cidx;
#pragma unroll
        for (int rt = 0; rt < 2; rt++) {
            const int rl = rloc0 + rt * 16;
            float* op = g_Opart + ((size_t)slot * 128 + rl) * 128;
#pragma unroll
            for (int nt = 0; nt < 16; nt++) {
                int cc = nt * 8 + cl0;
                *(float2*)(op + cc)           = make_float2(o_acc[rt][nt][0], o_acc[rt][nt][1]);
                *(float2*)(op + 8 * 128 + cc) = make_float2(o_acc[rt][nt][2], o_acc[rt][nt][3]);
            }
            if ((lane & 3) == 0) {
                g_lpart[slot * 128 + rl]     = ls[rt][0];
                g_lpart[slot * 128 + rl + 8] = ls[rt][1];
            }
        }
    }
}

// ---------------- combine split-KV partials ----------------
__global__ __launch_bounds__(256) void combine_kernel(float* __restrict__ out)
{
    const int qt = blockIdx.x, b = blockIdx.y, z = blockIdx.z;
    const int s = (qt + 9) / 9;
    if (s < 2) return;
    __shared__ float linv[128];
    const int tid = threadIdx.x;
    const int slot0 = (b * 32 + qt) * 4;
    if (tid < 128) {
        float l = g_lpart[slot0 * 128 + tid] + g_lpart[(slot0 + 1) * 128 + tid];
        if (s > 2) l += g_lpart[(slot0 + 2) * 128 + tid];
        if (s > 3) l += g_lpart[(slot0 + 3) * 128 + tid];
        linv[tid] = 1.0f / l;
    }
    __syncthreads();
    const float4* p0 = (const float4*)(g_Opart + (size_t)slot0 * 128 * 128);
    float4* ob = (float4*)(out + ((size_t)b * SS + qt * 128) * DD);
#pragma unroll
    for (int it = 0; it < 2; it++) {
        int e4 = z * 512 + it * 256 + tid;
        float4 a  = p0[e4];
        float4 x1 = p0[4096 + e4];
        float4 x2 = make_float4(0.f, 0.f, 0.f, 0.f);
        float4 x3 = make_float4(0.f, 0.f, 0.f, 0.f);
        if (s > 2) x2 = p0[2 * 4096 + e4];
        if (s > 3) x3 = p0[3 * 4096 + e4];
        a.x += x1.x + x2.x + x3.x;
        a.y += x1.y + x2.y + x3.y;
        a.z += x1.z + x2.z + x3.z;
        a.w += x1.w + x2.w + x3.w;
        float iv = linv[e4 >> 5];
        a.x *= iv; a.y *= iv; a.z *= iv; a.w *= iv;
        ob[e4] = a;
    }
}

// ---------------- launch ----------------
extern "C" void kernel_launch(void* const* d_in, const int* in_sizes, int n_in,
                              void* d_out, int out_size)
{
    const float* x  = (const float*)d_in[0];
    const float* Wq = (const float*)d_in[1];
    const float* Wk = (const float*)d_in[2];
    const float* Wv = (const float*)d_in[3];
    float* out = (float*)d_out;

    cudaFuncSetAttribute(proj_mma,  cudaFuncAttributeMaxDynamicSharedMemorySize, PJ_SMEM);
    cudaFuncSetAttribute(flash_mma, cudaFuncAttributeMaxDynamicSharedMemorySize, FL_SMEM);

    wconv_kernel<<<(3 * EE * DD / 4 + 255) / 256, 256>>>(Wq, Wk, Wv);
    proj_mma<<<dim3(3, 128), 256, PJ_SMEM>>>(x);
    flash_mma<<<296, 128, FL_SMEM>>>(out);
    combine_kernel<<<dim3(32, 4, 8), 256>>>(out);
}

// round 16
// speedup vs baseline: 1.0551x; 1.0551x over previous
#include <cuda_runtime.h>
#include <cuda_fp16.h>
#include <cstdint>

#define BB 4
#define SS 4096
#define EE 1024
#define DD 128
#define QSCALE (0.03125f * 1.4426950408889634f)   // (1/sqrt(1024)) * log2(e)

// ---------------- device scratch ----------------
__device__ __align__(16) __half g_Wh[3*EE*DD];     // [o][e][n] fp16
__device__ __align__(16) __half g_Qh[BB*SS*DD];    // pre-scaled by QSCALE
__device__ __align__(16) __half g_Kh[BB*SS*DD];
__device__ __align__(16) __half g_Vh[BB*SS*DD];
__device__ __align__(16) float  g_Opart[(size_t)BB*32*4*128*128];  // [b][qt][slot][128][128]
__device__ __align__(16) float  g_lpart[BB*32*4*128];              // [b][qt][slot][row]

// Unit schedule: 74 chunk-units per batch sorted by size (tiles) DESCENDING.
// code = qt*4 + cidx. Pairing rank r with 73-r then gives max pair sum 15
// (vs 18 with qt-descending order) -> balanced per-SM work.
__constant__ uint8_t g_sched[74] = {
    // size 9 (10)
    32, 64, 68, 69, 96, 100, 101, 104, 105, 106,
    // size 8 (24)
    28, 56, 60, 61, 65, 84, 88, 89, 92, 93, 94, 97, 98, 102,
    112, 116, 117, 120, 121, 122, 124, 125, 126, 127,
    // size 7 (24)
    24, 48, 52, 53, 57, 72, 76, 77, 80, 81, 82, 85, 86, 90,
    108, 109, 110, 111, 113, 114, 115, 118, 119, 123,
    // size 6 (8)
    20, 40, 44, 45, 49, 73, 74, 78,
    // size 5 (4)
    16, 36, 37, 41,
    // sizes 4,3,2,1
    12, 8, 4, 0
};

// ---------------- helpers ----------------
__device__ __forceinline__ uint32_t smem_u32(const void* p) {
    uint32_t a;
    asm("{ .reg .u64 t; cvta.to.shared.u64 t, %1; cvt.u32.u64 %0, t; }" : "=r"(a) : "l"(p));
    return a;
}
__device__ __forceinline__ void ldsm4(uint32_t& r0, uint32_t& r1, uint32_t& r2, uint32_t& r3, uint32_t addr) {
    asm volatile("ldmatrix.sync.aligned.m8n8.x4.shared.b16 {%0,%1,%2,%3}, [%4];"
        : "=r"(r0), "=r"(r1), "=r"(r2), "=r"(r3) : "r"(addr));
}
__device__ __forceinline__ void ldsm4t(uint32_t& r0, uint32_t& r1, uint32_t& r2, uint32_t& r3, uint32_t addr) {
    asm volatile("ldmatrix.sync.aligned.m8n8.x4.trans.shared.b16 {%0,%1,%2,%3}, [%4];"
        : "=r"(r0), "=r"(r1), "=r"(r2), "=r"(r3) : "r"(addr));
}
__device__ __forceinline__ void mma16816(float* d, const uint32_t* a, uint32_t b0, uint32_t b1) {
    asm volatile("mma.sync.aligned.m16n8k16.row.col.f32.f16.f16.f32 "
        "{%0,%1,%2,%3},{%4,%5,%6,%7},{%8,%9},{%0,%1,%2,%3};"
        : "+f"(d[0]), "+f"(d[1]), "+f"(d[2]), "+f"(d[3])
        : "r"(a[0]), "r"(a[1]), "r"(a[2]), "r"(a[3]), "r"(b0), "r"(b1));
}
// fp16-accumulator MMA: D,C are 2x uint32 (half2 pairs)
__device__ __forceinline__ void mma16816h(uint32_t* d, const uint32_t* a, uint32_t b0, uint32_t b1) {
    asm volatile("mma.sync.aligned.m16n8k16.row.col.f16.f16.f16.f16 "
        "{%0,%1},{%2,%3,%4,%5},{%6,%7},{%0,%1};"
        : "+r"(d[0]), "+r"(d[1])
        : "r"(a[0]), "r"(a[1]), "r"(a[2]), "r"(a[3]), "r"(b0), "r"(b1));
}
__device__ __forceinline__ void cpa16(uint32_t dst, const void* src) {
    asm volatile("cp.async.ca.shared.global [%0], [%1], 16;" :: "r"(dst), "l"(src));
}
#define CPC()  asm volatile("cp.async.commit_group;" ::: "memory")
#define CPW0() asm volatile("cp.async.wait_group 0;" ::: "memory")
#define CPW1() asm volatile("cp.async.wait_group 1;" ::: "memory")

__device__ __forceinline__ uint32_t packh2(float lo, float hi) {
    __half2 h = __floats2half2_rn(lo, hi);
    return *(uint32_t*)&h;
}
// 2^x on a packed half2 (one MUFU op)
__device__ __forceinline__ uint32_t ex2h2(uint32_t x) {
    uint32_t d;
    asm("ex2.approx.f16x2 %0, %1;" : "=r"(d) : "r"(x));
    return d;
}
__device__ __forceinline__ uint32_t hadd2(uint32_t a, uint32_t b) {
    uint32_t d;
    asm("add.rn.f16x2 %0, %1, %2;" : "=r"(d) : "r"(a), "r"(b));
    return d;
}

// ---------------- W convert (vectorized) ----------------
__global__ void wconv_kernel(const float* __restrict__ Wq, const float* __restrict__ Wk,
                             const float* __restrict__ Wv)
{
    int i4 = blockIdx.x * blockDim.x + threadIdx.x;
    if (i4 >= 3 * EE * DD / 4) return;
    int o = i4 >> 15, r = i4 & 32767;
    const float* W = (o == 0) ? Wq : (o == 1) ? Wk : Wv;
    float4 v = ((const float4*)W)[r];
    uint2 h;
    h.x = packh2(v.x, v.y);
    h.y = packh2(v.z, v.w);
    ((uint2*)(g_Wh + (size_t)o * EE * DD))[r] = h;
}

// ---------------- projection: Y[m,128] = X[m,1024] @ W ----------------
#define PXSTR 72
#define PWSTR 136
#define PX_TILE (128*PXSTR)         // halves, x2 buffers
#define PW_TILE (64*PWSTR)          // halves, x2 buffers
#define PJ_SMEM ((2*PX_TILE + 2*PW_TILE)*2)   // 71,680 bytes

__global__ __launch_bounds__(256, 2) void proj_mma(const float* __restrict__ X)
{
    extern __shared__ __align__(16) __half sm[];
    __half* Xh = sm;                       // 2 buffers
    __half* Wh = sm + 2 * PX_TILE;         // 2 buffers

    const int tid  = threadIdx.x;
    const int lane = tid & 31;
    const int warp = tid >> 5;
    const int o = blockIdx.x, mt = blockIdx.y;
    const int m0 = mt * 128;

    const int xrow = tid >> 1;
    const int xcol = (tid & 1) * 32;
    const float* xbase = X + (size_t)(m0 + xrow) * EE + xcol;
    const __half* wh_src = g_Wh + (size_t)o * EE * DD;   // [e][n]

    // ---- prologue: X0 -> xb0, issue W0 ----
    float4 xr[8];
#pragma unroll
    for (int j = 0; j < 8; j++) xr[j] = ((const float4*)xbase)[j];
    {
        __half* xh = Xh + xrow * PXSTR + xcol;
#pragma unroll
        for (int j = 0; j < 8; j++) {
            float4 v = xr[j];
            ((uint32_t*)(xh + j * 4))[0] = packh2(v.x, v.y);
            ((uint32_t*)(xh + j * 4))[1] = packh2(v.z, v.w);
        }
    }
#pragma unroll
    for (int j = 0; j < 4; j++) {
        int idx = tid + j * 256;
        int r = idx >> 4, c8 = (idx & 15) * 8;
        cpa16(smem_u32(Wh + r * PWSTR + c8), wh_src + (size_t)r * DD + c8);
    }
    CPC();
#pragma unroll
    for (int j = 0; j < 8; j++) xr[j] = ((const float4*)(xbase + 64))[j];

    float acc[16][4];
#pragma unroll
    for (int i = 0; i < 16; i++)
#pragma unroll
        for (int j = 0; j < 4; j++) acc[i][j] = 0.f;

    const uint32_t lbX = (((uint32_t)(lane & 15)) * PXSTR + ((uint32_t)(lane >> 4)) * 8) * 2;
    const uint32_t lbW = (((uint32_t)(lane & 15)) * PWSTR + ((uint32_t)(lane >> 4)) * 8) * 2;

    for (int c = 0; c < 16; c++) {
        CPW0();            // W(c) data arrived
        __syncthreads();   // all warps done with compute(c-1): buffers (c+1)&1 now safe

        if (c + 1 < 16) {
            // STS X(c+1) into other buffer
            __half* xh = Xh + ((c + 1) & 1) * PX_TILE + xrow * PXSTR + xcol;
#pragma unroll
            for (int j = 0; j < 8; j++) {
                float4 v = xr[j];
                ((uint32_t*)(xh + j * 4))[0] = packh2(v.x, v.y);
                ((uint32_t*)(xh + j * 4))[1] = packh2(v.z, v.w);
            }
            // issue W(c+1) copy — overlaps with compute(c)
            const int nb = (c + 1) & 1;
#pragma unroll
            for (int j = 0; j < 4; j++) {
                int idx = tid + j * 256;
                int r = idx >> 4, c8 = (idx & 15) * 8;
                cpa16(smem_u32(Wh + nb * PW_TILE + r * PWSTR + c8),
                      wh_src + (size_t)((c + 1) * 64 + r) * DD + c8);
            }
            CPC();
            if (c + 2 < 16) {
#pragma unroll
                for (int j = 0; j < 8; j++) xr[j] = ((const float4*)(xbase + (c + 2) * 64))[j];
            }
        }

        const uint32_t xhb = smem_u32(Xh + (c & 1) * PX_TILE) + (uint32_t)warp * 16 * PXSTR * 2 + lbX;
        const uint32_t whb = smem_u32(Wh + (c & 1) * PW_TILE) + lbW;

        uint32_t afh[4][4];
#pragma unroll
        for (int j = 0; j < 4; j++)
            ldsm4(afh[j][0], afh[j][1], afh[j][2], afh[j][3], xhb + j * 32);
#pragma unroll
        for (int t2 = 0; t2 < 8; t2++) {
#pragma unroll
            for (int kk = 0; kk < 4; kk++) {
                uint32_t w0, w1, w2, w3;
                ldsm4t(w0, w1, w2, w3, whb + (uint32_t)kk * 16 * PWSTR * 2 + t2 * 32);
                mma16816(acc[2 * t2],     afh[kk], w0, w1);
                mma16816(acc[2 * t2 + 1], afh[kk], w2, w3);
            }
        }
    }

    // ---- epilogue ----
    const int r0 = m0 + warp * 16 + (lane >> 2);
    const int r1 = r0 + 8;
    __half* dst = (o == 0) ? g_Qh : (o == 1) ? g_Kh : g_Vh;
    const float sc = (o == 0) ? QSCALE : 1.0f;
#pragma unroll
    for (int nt = 0; nt < 16; nt++) {
        int cc = nt * 8 + (lane & 3) * 2;
        *(uint32_t*)(dst + (size_t)r0 * DD + cc) = packh2(acc[nt][0] * sc, acc[nt][1] * sc);
        *(uint32_t*)(dst + (size_t)r1 * DD + cc) = packh2(acc[nt][2] * sc, acc[nt][3] * sc);
    }
}

// ---------------- flash attention: 4 warps x 32 q-rows, ring-of-3 KV pairs ----------------
#define FSTR 136
#define FKV_TILE (64*FSTR)          // halves per 64-row tile (one ring slot)
#define FL_SMEM (6*FKV_TILE*2)      // 104,448 bytes (slots 0-1 initially hold Q)
#define HNEG 0xFBFFu                // fp16 -65504

__device__ __forceinline__ void cp_tile64(__half* dst, const __half* src, int tid) {
#pragma unroll
    for (int j = 0; j < 8; j++) {
        int idx = tid + j * 128;
        int r = idx >> 4, cc = (idx & 15) * 8;
        cpa16(smem_u32(dst + r * FSTR + cc), src + (size_t)r * DD + cc);
    }
}

// S-MMA (fp16 accumulate) for one 16-col sub-tile t: dst[rt][nh][rowhalf] as half2
__device__ __forceinline__ void s_mma_step(uint32_t (&dst)[2][2][2], uint32_t kbb, int t,
                                           const uint32_t (&qf)[2][8][4]) {
#pragma unroll
    for (int rt = 0; rt < 2; rt++)
#pragma unroll
        for (int nh = 0; nh < 2; nh++)
#pragma unroll
            for (int h = 0; h < 2; h++) dst[rt][nh][h] = 0u;
#pragma unroll
    for (int j = 0; j < 8; j++) {
        uint32_t k0, k1, k2, k3;
        ldsm4(k0, k1, k2, k3, kbb + (uint32_t)t * 16 * FSTR * 2 + j * 32);
        mma16816h(dst[0][0], qf[0][j], k0, k2);
        mma16816h(dst[0][1], qf[0][j], k1, k3);
        mma16816h(dst[1][0], qf[1][j], k0, k2);
        mma16816h(dst[1][1], qf[1][j], k1, k3);
    }
}

// chunk units: s(qt) = ceil((qt+1)/9); grid = 296 = 2 CTAs x 148 SMs
__global__ __launch_bounds__(128, 2) void flash_mma(float* __restrict__ out)
{
    extern __shared__ __align__(16) __half sm[];
    const uint32_t smb = smem_u32(sm);

    const int tid  = threadIdx.x;
    const int lane = tid & 31;
    const int warp = tid >> 5;

    // bid and bid+148 land on the same SM; pair sorted-rank g with 295-g.
    const int idx = (blockIdx.x < 148) ? blockIdx.x : (443 - blockIdx.x);
    const int bz = idx & 3;
    const int vv = idx >> 2;                 // per-batch rank, size-descending
    const int code = g_sched[vv];
    const int qt = code >> 2;
    const int cidx = code & 3;
    const int nn = qt + 1;
    const int s = (nn + 8) / 9;
    const int cb_sz = nn / s, cb_rem = nn % s;
    const int t0 = cidx * cb_sz + (cidx < cb_rem ? cidx : cb_rem);
    const int sz128 = cb_sz + (cidx < cb_rem ? 1 : 0);
    const int u0 = 2 * t0;
    const int nit = 2 * sz128;          // iterations (>= 2)
    const int q0 = qt * 128;

    const __half* Qg = g_Qh + (size_t)(bz * SS + q0) * DD;
    const __half* Kg = g_Kh + (size_t)bz * SS * DD;
    const __half* Vg = g_Vh + (size_t)bz * SS * DD;

    // initial loads: Q -> slots 0,1 ; pair0 (K,V) -> slots 2,3 ; pair1 -> slots 4,5
    cp_tile64((__half*)sm,                Qg, tid);
    cp_tile64((__half*)sm + FKV_TILE,     Qg + (size_t)64 * DD, tid);
    cp_tile64((__half*)sm + 2 * FKV_TILE, Kg + (size_t)u0 * 64 * DD, tid);
    cp_tile64((__half*)sm + 3 * FKV_TILE, Vg + (size_t)u0 * 64 * DD, tid);
    CPC();   // group A: Q + pair0
    cp_tile64((__half*)sm + 4 * FKV_TILE, Kg + (size_t)(u0 + 1) * 64 * DD, tid);
    cp_tile64((__half*)sm + 5 * FKV_TILE, Vg + (size_t)(u0 + 1) * 64 * DD, tid);
    CPC();   // group B: pair1

    float o_acc[2][16][4];
#pragma unroll
    for (int rt = 0; rt < 2; rt++)
#pragma unroll
        for (int i = 0; i < 16; i++)
#pragma unroll
            for (int j = 0; j < 4; j++) o_acc[rt][i][j] = 0.f;
    float ls[2][2] = {{0.f, 0.f}, {0.f, 0.f}};

    const uint32_t lanebase = (((uint32_t)(lane & 15)) * FSTR + ((uint32_t)(lane >> 4)) * 8) * 2;
    const int rloc0 = warp * 32 + (lane >> 2);
    const int cl0 = (lane & 3) * 2;

    // ---- Q fragments (Q smem becomes ring slot 0/1 afterwards) ----
    uint32_t qf[2][8][4];
    CPW1();            // group A (Q + pair0) arrived
    __syncthreads();   // visible to all threads
#pragma unroll
    for (int rt = 0; rt < 2; rt++) {
        const uint32_t qb = smb + (uint32_t)(warp * 32 + rt * 16) * FSTR * 2 + lanebase;
#pragma unroll
        for (int j = 0; j < 8; j++)
            ldsm4(qf[rt][j][0], qf[rt][j][1], qf[rt][j][2], qf[rt][j][3], qb + j * 32);
    }

    for (int j = 0; j < nit; j++) {
        const int u = u0 + j;
        if (j < nit - 1) { CPW1(); } else { CPW0(); }
        __syncthreads();   // pair j visible; all warps done with pair j-1 (and qf loads on j=0)

        // prefetch pair j+2 into ring slot (j%3) — overlaps with compute below
        if (j + 2 < nit) {
            const int p = j % 3;
            cp_tile64((__half*)sm + (2 * p)     * FKV_TILE, Kg + (size_t)(u + 2) * 64 * DD, tid);
            cp_tile64((__half*)sm + (2 * p + 1) * FKV_TILE, Vg + (size_t)(u + 2) * 64 * DD, tid);
            CPC();
        }

        const int p = (j + 1) % 3;   // this iteration's pair: slots (2p, 2p+1)
        const uint32_t kbb = smb + (uint32_t)(2 * p) * FKV_TILE * 2 + lanebase;
        const uint32_t vbb = smb + (uint32_t)(2 * p + 1) * FKV_TILE * 2 + lanebase;
        const int kv0 = u * 64;
        const int dloc = u - 2 * qt;
        const bool diag = (dloc >= 0);
        const bool skipw = (dloc == 1) && (warp < 2);

        if (!skipw) {
            // per-tile half2 l accumulators (flushed to fp32 at tile end)
            uint32_t lh[2][2] = {{0u, 0u}, {0u, 0u}};
            // software-pipelined sub-tiles: S(t+1) issued before softmax(t)
            uint32_t sf[2][2][2][2];   // [buf][rt][nh][rowhalf] fp16x2 accumulators
            s_mma_step(sf[0], kbb, 0, qf);
#pragma unroll
            for (int t = 0; t < 4; t++) {
                if (t < 3) s_mma_step(sf[(t + 1) & 1], kbb, t + 1, qf);
                uint32_t (&sc)[2][2][2] = sf[t & 1];

                uint32_t pf[2][4];
#pragma unroll
                for (int rt = 0; rt < 2; rt++) {
                    if (diag) {
                        const int rg = q0 + rloc0 + rt * 16;
#pragma unroll
                        for (int nh = 0; nh < 2; nh++) {
                            const int cb = kv0 + t * 16 + nh * 8 + cl0;
                            // row r (low reg), cols cb, cb+1
                            uint32_t m0 = sc[rt][nh][0];
                            if (cb     > rg) m0 = (m0 & 0xFFFF0000u) | HNEG;
                            if (cb + 1 > rg) m0 = (m0 & 0x0000FFFFu) | (HNEG << 16);
                            sc[rt][nh][0] = m0;
                            // row r+8 (high reg)
                            uint32_t m1 = sc[rt][nh][1];
                            if (cb     > rg + 8) m1 = (m1 & 0xFFFF0000u) | HNEG;
                            if (cb + 1 > rg + 8) m1 = (m1 & 0x0000FFFFu) | (HNEG << 16);
                            sc[rt][nh][1] = m1;
                        }
                    }
                    // P fragments directly from fp16 accumulators (a0..a3 layout)
                    pf[rt][0] = ex2h2(sc[rt][0][0]);   // row r,   k nh0
                    pf[rt][1] = ex2h2(sc[rt][0][1]);   // row r+8, k nh0
                    pf[rt][2] = ex2h2(sc[rt][1][0]);   // row r,   k nh1
                    pf[rt][3] = ex2h2(sc[rt][1][1]);   // row r+8, k nh1
                    lh[rt][0] = hadd2(lh[rt][0], hadd2(pf[rt][0], pf[rt][2]));
                    lh[rt][1] = hadd2(lh[rt][1], hadd2(pf[rt][1], pf[rt][3]));
                }

                // O += P_t @ V_t (fp32 accumulate)
#pragma unroll
                for (int t2 = 0; t2 < 8; t2++) {
                    uint32_t v0, v1, v2, v3;
                    ldsm4t(v0, v1, v2, v3, vbb + (uint32_t)t * 16 * FSTR * 2 + t2 * 32);
                    mma16816(o_acc[0][2 * t2],     pf[0], v0, v1);
                    mma16816(o_acc[0][2 * t2 + 1], pf[0], v2, v3);
                    mma16816(o_acc[1][2 * t2],     pf[1], v0, v1);
                    mma16816(o_acc[1][2 * t2 + 1], pf[1], v2, v3);
                }
            }
            // flush per-tile half2 sums into fp32 ls
#pragma unroll
            for (int rt = 0; rt < 2; rt++) {
#pragma unroll
                for (int k = 0; k < 2; k++) {
                    __half2 h = *(__half2*)&lh[rt][k];
                    float2 f = __half22float2(h);
                    ls[rt][k] += f.x + f.y;
                }
            }
        }
    }

    // ---- epilogue ----
#pragma unroll
    for (int rt = 0; rt < 2; rt++) {
        ls[rt][0] += __shfl_xor_sync(0xffffffffu, ls[rt][0], 1);
        ls[rt][0] += __shfl_xor_sync(0xffffffffu, ls[rt][0], 2);
        ls[rt][1] += __shfl_xor_sync(0xffffffffu, ls[rt][1], 1);
        ls[rt][1] += __shfl_xor_sync(0xffffffffu, ls[rt][1], 2);
    }

    if (s == 1) {
#pragma unroll
        for (int rt = 0; rt < 2; rt++) {
            const float inv0 = 1.0f / ls[rt][0];
            const float inv1 = 1.0f / ls[rt][1];
            float* o0 = out + (size_t)(bz * SS + q0 + rloc0 + rt * 16) * DD;
            float* o1 = o0 + 8 * DD;
#pragma unroll
            for (int nt = 0; nt < 16; nt++) {
                int cc = nt * 8 + cl0;
                *(float2*)(o0 + cc) = make_float2(o_acc[rt][nt][0] * inv0, o_acc[rt][nt][1] * inv0);
                *(float2*)(o1 + cc) = make_float2(o_acc[rt][nt][2] * inv1, o_acc[rt][nt][3] * inv1);
            }
        }
    } else {
        const int slot = (bz * 32 + qt) * 4 + cidx;
#pragma unroll
        for (int rt = 0; rt < 2; rt++) {
            const int rl = rloc0 + rt * 16;
            float* op = g_Opart + ((size_t)slot * 128 + rl) * 128;
#pragma unroll
            for (int nt = 0; nt < 16; nt++) {
                int cc = nt * 8 + cl0;
                *(float2*)(op + cc)           = make_float2(o_acc[rt][nt][0], o_acc[rt][nt][1]);
                *(float2*)(op + 8 * 128 + cc) = make_float2(o_acc[rt][nt][2], o_acc[rt][nt][3]);
            }
            if ((lane & 3) == 0) {
                g_lpart[slot * 128 + rl]     = ls[rt][0];
                g_lpart[slot * 128 + rl + 8] = ls[rt][1];
            }
        }
    }
}

// ---------------- combine split-KV partials ----------------
__global__ __launch_bounds__(256) void combine_kernel(float* __restrict__ out)
{
    const int qt = blockIdx.x, b = blockIdx.y, z = blockIdx.z;
    const int s = (qt + 9) / 9;
    if (s < 2) return;
    __shared__ float linv[128];
    const int tid = threadIdx.x;
    const int slot0 = (b * 32 + qt) * 4;
    if (tid < 128) {
        float l = g_lpart[slot0 * 128 + tid] + g_lpart[(slot0 + 1) * 128 + tid];
        if (s > 2) l += g_lpart[(slot0 + 2) * 128 + tid];
        if (s > 3) l += g_lpart[(slot0 + 3) * 128 + tid];
        linv[tid] = 1.0f / l;
    }
    __syncthreads();
    const float4* p0 = (const float4*)(g_Opart + (size_t)slot0 * 128 * 128);
    float4* ob = (float4*)(out + ((size_t)b * SS + qt * 128) * DD);
#pragma unroll
    for (int it = 0; it < 2; it++) {
        int e4 = z * 512 + it * 256 + tid;
        float4 a  = p0[e4];
        float4 x1 = p0[4096 + e4];
        float4 x2 = make_float4(0.f, 0.f, 0.f, 0.f);
        float4 x3 = make_float4(0.f, 0.f, 0.f, 0.f);
        if (s > 2) x2 = p0[2 * 4096 + e4];
        if (s > 3) x3 = p0[3 * 4096 + e4];
        a.x += x1.x + x2.x + x3.x;
        a.y += x1.y + x2.y + x3.y;
        a.z += x1.z + x2.z + x3.z;
        a.w += x1.w + x2.w + x3.w;
        float iv = linv[e4 >> 5];
        a.x *= iv; a.y *= iv; a.z *= iv; a.w *= iv;
        ob[e4] = a;
    }
}

// ---------------- launch ----------------
extern "C" void kernel_launch(void* const* d_in, const int* in_sizes, int n_in,
                              void* d_out, int out_size)
{
    const float* x  = (const float*)d_in[0];
    const float* Wq = (const float*)d_in[1];
    const float* Wk = (const float*)d_in[2];
    const float* Wv = (const float*)d_in[3];
    float* out = (float*)d_out;

    cudaFuncSetAttribute(proj_mma,  cudaFuncAttributeMaxDynamicSharedMemorySize, PJ_SMEM);
    cudaFuncSetAttribute(flash_mma, cudaFuncAttributeMaxDynamicSharedMemorySize, FL_SMEM);

    wconv_kernel<<<(3 * EE * DD / 4 + 255) / 256, 256>>>(Wq, Wk, Wv);
    proj_mma<<<dim3(3, 128), 256, PJ_SMEM>>>(x);
    flash_mma<<<296, 128, FL_SMEM>>>(out);
    combine_kernel<<<dim3(32, 4, 8), 256>>>(out);
}